// round 1
// baseline (speedup 1.0000x reference)
#include <cuda_runtime.h>
#include <cuda_bf16.h>
#include <cstdint>

// Problem constants
#define BB 32
#define SS 100
#define TT 100
#define EE 128
#define HH 256
#define VV 32000
#define G3 (3*HH)      // 768
#define TV (TT*VV)     // 3,200,000 elements per batch row of output

// ---------------- device scratch (no allocs allowed) ----------------
__device__ float g_Xih[BB*SS*G3];        // precomputed x@enc_Wih^T + bih
__device__ float g_enc_outs[BB*SS*HH];
__device__ float g_enc_part[BB*SS];
__device__ float g_h[2][BB*HH];          // double-buffered hidden state
__device__ float g_ctx[BB*HH];
__device__ unsigned long long g_amax[2][BB];

// ---------------- helpers ----------------
__device__ __forceinline__ float sigf(float x) { return 1.0f / (1.0f + expf(-x)); }

__device__ __forceinline__ unsigned fkey(float f) {
    unsigned u = __float_as_uint(f);
    return (u & 0x80000000u) ? ~u : (u | 0x80000000u);
}

__device__ __forceinline__ unsigned long long pk2(float x, float y) {
    unsigned long long r;
    asm("mov.b64 %0, {%1, %2};" : "=l"(r) : "f"(x), "f"(y));
    return r;
}
__device__ __forceinline__ void upk2(unsigned long long p, float &x, float &y) {
    asm("mov.b64 {%0, %1}, %2;" : "=f"(x), "=f"(y) : "l"(p));
}
__device__ __forceinline__ unsigned long long fma2(unsigned long long a,
                                                   unsigned long long b,
                                                   unsigned long long c) {
    unsigned long long d;
    asm("fma.rn.f32x2 %0, %1, %2, %3;" : "=l"(d) : "l"(a), "l"(b), "l"(c));
    return d;
}

// ---------------- init: zero h0 ----------------
__global__ void k_init() {
    int i = blockIdx.x * blockDim.x + threadIdx.x;
    if (i < BB*HH) g_h[0][i] = 0.0f;
}

// ---------------- precompute encoder input gates ----------------
// grid (SS, BB), block 256
__global__ void k_xih(const int* __restrict__ ing, const float* __restrict__ emb,
                      const float* __restrict__ Wih, const float* __restrict__ bih) {
    int s = blockIdx.x, b = blockIdx.y;
    __shared__ float xs[EE];
    int tid = threadIdx.x;
    int tok = ing[b*SS + s];
    if (tid < EE) xs[tid] = emb[tok*EE + tid];
    __syncthreads();
    const float4* x4 = (const float4*)xs;
    #pragma unroll
    for (int i = 0; i < 3; i++) {
        int j = tid + i*256;
        const float4* w4 = (const float4*)(Wih + j*EE);
        float acc = bih[j];
        #pragma unroll
        for (int k = 0; k < EE/4; k++) {
            float4 w = __ldg(&w4[k]);
            float4 xv = x4[k];
            acc += w.x*xv.x + w.y*xv.y + w.z*xv.z + w.w*xv.w;
        }
        g_Xih[(b*SS + s)*G3 + j] = acc;
    }
}

// ---------------- encoder recurrence step ----------------
// grid 64, block (32,4); thread = (b, j-within-chunk)
__global__ void __launch_bounds__(128) k_enc(int s, const float* __restrict__ Whh,
                                             const float* __restrict__ bhh) {
    __shared__ float hs[HH*BB];   // hs[k*32 + b]
    const float* hin = g_h[s & 1];
    float* hout = g_h[(s + 1) & 1];
    int b = threadIdx.x, ty = threadIdx.y;
    int l = ty*32 + b;
    for (int idx = l; idx < BB*HH; idx += 128)
        hs[(idx & (HH-1))*32 + (idx >> 8)] = hin[idx];
    __syncthreads();
    int j = blockIdx.x*4 + ty;
    const float4* wr = (const float4*)(Whh + j*HH);
    const float4* wz = (const float4*)(Whh + (HH + j)*HH);
    const float4* wn = (const float4*)(Whh + (2*HH + j)*HH);
    float hr = bhh[j], hz = bhh[HH + j], hn = bhh[2*HH + j];
    #pragma unroll 4
    for (int k4 = 0; k4 < HH/4; k4++) {
        float4 a = __ldg(&wr[k4]);
        float4 c = __ldg(&wz[k4]);
        float4 d = __ldg(&wn[k4]);
        int k = k4*4;
        float h0 = hs[(k+0)*32+b], h1 = hs[(k+1)*32+b];
        float h2v = hs[(k+2)*32+b], h3 = hs[(k+3)*32+b];
        hr += a.x*h0 + a.y*h1 + a.z*h2v + a.w*h3;
        hz += c.x*h0 + c.y*h1 + c.z*h2v + c.w*h3;
        hn += d.x*h0 + d.y*h1 + d.z*h2v + d.w*h3;
    }
    const float* gi = &g_Xih[(b*SS + s)*G3];
    float r = sigf(gi[j] + hr);
    float z = sigf(gi[HH + j] + hz);
    float n = tanhf(gi[2*HH + j] + r*hn);
    float hp = hs[j*32 + b];
    float h2 = (1.0f - z)*n + z*hp;
    hout[b*HH + j] = h2;
    g_enc_outs[(b*SS + s)*HH + j] = h2;
}

// ---------------- precompute attention encoder part ----------------
__global__ void k_encpart(const float* __restrict__ attn_W, const float* __restrict__ attn_b) {
    int i = blockIdx.x*blockDim.x + threadIdx.x;
    if (i >= BB*SS) return;
    const float4* e4 = (const float4*)(g_enc_outs + (size_t)i*HH);
    const float4* w4 = (const float4*)attn_W;   // first H entries = w_e
    float acc = attn_b[0];
    #pragma unroll 8
    for (int k = 0; k < HH/4; k++) {
        float4 e = e4[k];
        float4 w = __ldg(&w4[k]);
        acc += e.x*w.x + e.y*w.y + e.z*w.z + e.w*w.w;
    }
    g_enc_part[i] = acc;
}

// ---------------- attention (per decoder step) ----------------
// grid BB, block 128
__global__ void __launch_bounds__(128) k_attn(int t, const float* __restrict__ attn_W) {
    int b = blockIdx.x, tid = threadIdx.x;
    const float* h = g_h[t & 1];
    __shared__ float red[128];
    __shared__ float ws[128];
    if (tid == 0) g_amax[t & 1][b] = 0ULL;   // reset slot for this step's logits

    // hw = dot(h[b], w_h)
    float p = h[b*HH + tid]*attn_W[HH + tid] + h[b*HH + 128 + tid]*attn_W[HH + 128 + tid];
    red[tid] = p; __syncthreads();
    for (int o = 64; o > 0; o >>= 1) { if (tid < o) red[tid] += red[tid + o]; __syncthreads(); }
    float hw = red[0]; __syncthreads();

    float sc = (tid < SS) ? (g_enc_part[b*SS + tid] + hw) : -1e30f;
    red[tid] = sc; __syncthreads();
    for (int o = 64; o > 0; o >>= 1) { if (tid < o) red[tid] = fmaxf(red[tid], red[tid + o]); __syncthreads(); }
    float mx = red[0]; __syncthreads();

    float e = (tid < SS) ? expf(sc - mx) : 0.0f;
    ws[tid] = e;
    red[tid] = e; __syncthreads();
    for (int o = 64; o > 0; o >>= 1) { if (tid < o) red[tid] += red[tid + o]; __syncthreads(); }
    float inv = 1.0f / red[0];
    __syncthreads();

    // ctx[b][j] = inv * sum_s e_s * enc_outs[b][s][j]
    #pragma unroll
    for (int i = 0; i < 2; i++) {
        int jj = tid + i*128;
        float acc = 0.0f;
        const float* eo = g_enc_outs + (size_t)b*SS*HH + jj;
        #pragma unroll 4
        for (int s = 0; s < SS; s++) acc += ws[s] * eo[s*HH];
        g_ctx[b*HH + jj] = acc * inv;
    }
}

// ---------------- decoder GRU step ----------------
// grid 64, block (32,4)
__global__ void __launch_bounds__(128) k_gru(int t, const float* __restrict__ emb,
                                             const float* __restrict__ Wih,
                                             const float* __restrict__ Whh,
                                             const float* __restrict__ bih,
                                             const float* __restrict__ bhh) {
    __shared__ float buf[HH*BB];   // 32 KB, reused for h then x chunks
    __shared__ int toks[BB];
    const float* hin = g_h[t & 1];
    float* hout = g_h[(t + 1) & 1];
    int b = threadIdx.x, ty = threadIdx.y;
    int l = ty*32 + b;
    if (l < BB)
        toks[l] = (t == 0) ? 1
                  : (int)(0xFFFFFFFFu - (unsigned)(g_amax[(t - 1) & 1][l] & 0xFFFFFFFFull));
    // fill h (k-major)
    for (int idx = l; idx < BB*HH; idx += 128)
        buf[(idx & (HH-1))*32 + (idx >> 8)] = hin[idx];
    __syncthreads();

    int j = blockIdx.x*4 + ty;
    // --- gh = h @ Whh^T + bhh ---
    float hr = bhh[j], hz = bhh[HH + j], hn = bhh[2*HH + j];
    {
        const float4* wr = (const float4*)(Whh + j*HH);
        const float4* wz = (const float4*)(Whh + (HH + j)*HH);
        const float4* wn = (const float4*)(Whh + (2*HH + j)*HH);
        #pragma unroll 4
        for (int k4 = 0; k4 < HH/4; k4++) {
            float4 a = __ldg(&wr[k4]);
            float4 c = __ldg(&wz[k4]);
            float4 d = __ldg(&wn[k4]);
            int k = k4*4;
            float h0 = buf[(k+0)*32+b], h1 = buf[(k+1)*32+b];
            float h2v = buf[(k+2)*32+b], h3 = buf[(k+3)*32+b];
            hr += a.x*h0 + a.y*h1 + a.z*h2v + a.w*h3;
            hz += c.x*h0 + c.y*h1 + c.z*h2v + c.w*h3;
            hn += d.x*h0 + d.y*h1 + d.z*h2v + d.w*h3;
        }
    }
    float hp = buf[j*32 + b];
    __syncthreads();   // everyone done reading h before overwrite

    // --- gi = x @ Wih^T + bih, x = [emb[tok], ctx], length 384, two 192-chunks ---
    float ir = bih[j], iz = bih[HH + j], inn = bih[2*HH + j];
    const float* rowr = Wih + j*(EE+HH);
    const float* rowz = Wih + (HH + j)*(EE+HH);
    const float* rown = Wih + (2*HH + j)*(EE+HH);
    #pragma unroll
    for (int ch = 0; ch < 2; ch++) {
        int kbase = ch*192;
        // fill chunk
        for (int idx = l; idx < 192*BB; idx += 128) {
            int bb = idx / 192, kk = idx % 192;
            int k = kbase + kk;
            float v = (k < EE) ? emb[toks[bb]*EE + k] : g_ctx[bb*HH + (k - EE)];
            buf[kk*32 + bb] = v;
        }
        __syncthreads();
        const float4* wr = (const float4*)(rowr + kbase);
        const float4* wz = (const float4*)(rowz + kbase);
        const float4* wn = (const float4*)(rown + kbase);
        #pragma unroll 4
        for (int k4 = 0; k4 < 48; k4++) {
            float4 a = __ldg(&wr[k4]);
            float4 c = __ldg(&wz[k4]);
            float4 d = __ldg(&wn[k4]);
            int k = k4*4;
            float x0 = buf[(k+0)*32+b], x1 = buf[(k+1)*32+b];
            float x2 = buf[(k+2)*32+b], x3 = buf[(k+3)*32+b];
            ir  += a.x*x0 + a.y*x1 + a.z*x2 + a.w*x3;
            iz  += c.x*x0 + c.y*x1 + c.z*x2 + c.w*x3;
            inn += d.x*x0 + d.y*x1 + d.z*x2 + d.w*x3;
        }
        __syncthreads();
    }

    float r = sigf(ir + hr);
    float z = sigf(iz + hz);
    float n = tanhf(inn + r*hn);
    float h2 = (1.0f - z)*n + z*hp;
    hout[b*HH + j] = h2;
}

// ---------------- logits + argmax (per decoder step) ----------------
// grid 125, block 256; thread owns one vocab row, 32 batch accumulators packed f32x2
__global__ void __launch_bounds__(256) k_logits(int t, const float* __restrict__ oW,
                                                const float* __restrict__ ob,
                                                float* __restrict__ out) {
    __shared__ float hs[HH*BB];                 // hs[k*32 + b], 32 KB
    __shared__ unsigned long long slots[BB];
    const float* h = g_h[(t + 1) & 1];
    int tid = threadIdx.x;
    if (tid < BB) slots[tid] = 0ULL;
    for (int idx = tid; idx < BB*HH; idx += 256)
        hs[(idx & (HH-1))*32 + (idx >> 8)] = h[idx];
    __syncthreads();

    int v = blockIdx.x*256 + tid;
    float bias = ob[v];
    unsigned long long acc[16];
    unsigned long long binit = pk2(bias, bias);
    #pragma unroll
    for (int i = 0; i < 16; i++) acc[i] = binit;

    const float4* w4 = (const float4*)(oW + (size_t)v*HH);
    #pragma unroll 2
    for (int k4 = 0; k4 < HH/4; k4++) {
        float4 w = __ldg(&w4[k4]);
        const float wv[4] = {w.x, w.y, w.z, w.w};
        #pragma unroll
        for (int sub = 0; sub < 4; sub++) {
            unsigned long long ww = pk2(wv[sub], wv[sub]);
            const ulonglong2* hp = (const ulonglong2*)(hs + (k4*4 + sub)*32);
            #pragma unroll
            for (int i = 0; i < 8; i++) {
                ulonglong2 hv = hp[i];
                acc[2*i]     = fma2(ww, hv.x, acc[2*i]);
                acc[2*i + 1] = fma2(ww, hv.y, acc[2*i + 1]);
            }
        }
    }

    // write logits (coalesced per b) + argmax reduction
    #pragma unroll
    for (int i = 0; i < 16; i++) {
        float f0, f1;
        upk2(acc[i], f0, f1);
        int b0 = 2*i, b1 = 2*i + 1;
        out[(size_t)b0*TV + v] = f0;
        out[(size_t)b1*TV + v] = f1;
        {
            unsigned key = fkey(f0);
            unsigned wmax = __reduce_max_sync(0xffffffffu, key);
            unsigned mask = __ballot_sync(0xffffffffu, key == wmax);
            if ((tid & 31) == (__ffs(mask) - 1))
                atomicMax(&slots[b0], ((unsigned long long)wmax << 32)
                                      | (unsigned long long)(0xFFFFFFFFu - (unsigned)v));
        }
        {
            unsigned key = fkey(f1);
            unsigned wmax = __reduce_max_sync(0xffffffffu, key);
            unsigned mask = __ballot_sync(0xffffffffu, key == wmax);
            if ((tid & 31) == (__ffs(mask) - 1))
                atomicMax(&slots[b1], ((unsigned long long)wmax << 32)
                                      | (unsigned long long)(0xFFFFFFFFu - (unsigned)v));
        }
    }
    __syncthreads();
    if (tid < BB) atomicMax(&g_amax[t & 1][tid], slots[tid]);
}

// ---------------- host launch ----------------
extern "C" void kernel_launch(void* const* d_in, const int* in_sizes, int n_in,
                              void* d_out, int out_size) {
    const int*   ing      = (const int*)d_in[0];
    const float* emb      = (const float*)d_in[1];
    const float* enc_Wih  = (const float*)d_in[2];
    const float* enc_Whh  = (const float*)d_in[3];
    const float* enc_bih  = (const float*)d_in[4];
    const float* enc_bhh  = (const float*)d_in[5];
    const float* dec_Wih  = (const float*)d_in[6];
    const float* dec_Whh  = (const float*)d_in[7];
    const float* dec_bih  = (const float*)d_in[8];
    const float* dec_bhh  = (const float*)d_in[9];
    const float* attn_W   = (const float*)d_in[10];
    const float* attn_b   = (const float*)d_in[11];
    const float* out_W    = (const float*)d_in[12];
    const float* out_b    = (const float*)d_in[13];
    float* out = (float*)d_out;

    k_init<<<8, 1024>>>();
    k_xih<<<dim3(SS, BB), 256>>>(ing, emb, enc_Wih, enc_bih);
    for (int s = 0; s < SS; s++)
        k_enc<<<64, dim3(32, 4)>>>(s, enc_Whh, enc_bhh);
    k_encpart<<<(BB*SS + 255)/256, 256>>>(attn_W, attn_b);
    for (int t = 0; t < TT; t++) {
        k_attn<<<BB, 128>>>(t, attn_W);
        k_gru<<<64, dim3(32, 4)>>>(t, emb, dec_Wih, dec_Whh, dec_bih, dec_bhh);
        k_logits<<<125, 256>>>(t, out_W, out_b, out + (size_t)t*VV);
    }
}

// round 2
// speedup vs baseline: 1.6502x; 1.6502x over previous
#include <cuda_runtime.h>
#include <cuda_bf16.h>
#include <cstdint>

#define BB 32
#define SS 100
#define TT 100
#define EE 128
#define HH 256
#define VV 32000
#define G3 (3*HH)
#define TV (TT*VV)
#define GRIDN 148

// ---------------- device scratch ----------------
__device__ float g_Xih[BB*SS*G3];
__device__ float g_enc_outs[BB*SS*HH];
__device__ float g_enc_part[BB*SS];
__device__ float g_h[2][BB*HH];
__device__ float g_ctx[BB*HH];
__device__ unsigned long long g_amax[2][BB];
__device__ unsigned g_ctr;

// ---------------- helpers ----------------
__device__ __forceinline__ float sigf(float x) { return 1.0f / (1.0f + expf(-x)); }

__device__ __forceinline__ unsigned fkey(float f) {
    unsigned u = __float_as_uint(f);
    return (u & 0x80000000u) ? ~u : (u | 0x80000000u);
}
__device__ __forceinline__ unsigned long long pk2(float x, float y) {
    unsigned long long r;
    asm("mov.b64 %0, {%1, %2};" : "=l"(r) : "f"(x), "f"(y));
    return r;
}
__device__ __forceinline__ void upk2(unsigned long long p, float &x, float &y) {
    asm("mov.b64 {%0, %1}, %2;" : "=f"(x), "=f"(y) : "l"(p));
}
__device__ __forceinline__ unsigned long long fma2(unsigned long long a,
                                                   unsigned long long b,
                                                   unsigned long long c) {
    unsigned long long d;
    asm("fma.rn.f32x2 %0, %1, %2, %3;" : "=l"(d) : "l"(a), "l"(b), "l"(c));
    return d;
}

// grid barrier: monotonic counter, release fence + acquire poll.
__device__ __forceinline__ void gbar(int &nbar) {
    __syncthreads();
    if (threadIdx.x == 0) {
        __threadfence();                       // release (drains stores, IVALL)
        unsigned tgt = (unsigned)(nbar + 1) * GRIDN;
        atomicAdd(&g_ctr, 1u);
        unsigned iter = 0;
        while (true) {
            unsigned v;
            asm volatile("ld.acquire.gpu.global.u32 %0, [%1];" : "=r"(v) : "l"(&g_ctr));
            if (v >= tgt) break;
            if (++iter > 4000000u) break;      // deadlock guard (never hang)
            __nanosleep(32);
        }
        __threadfence();                       // acquire side: IVALL this SM's L1D
    }
    nbar++;
    __syncthreads();
}

__global__ void k_reset() { g_ctr = 0u; }

// reduce helpers (256 threads)
__device__ __forceinline__ float rsum256(float v, float* red) {
    int tid = threadIdx.x;
    red[tid] = v; __syncthreads();
    #pragma unroll
    for (int o = 128; o > 0; o >>= 1) { if (tid < o) red[tid] += red[tid + o]; __syncthreads(); }
    float r = red[0]; __syncthreads();
    return r;
}
__device__ __forceinline__ float rmax256(float v, float* red) {
    int tid = threadIdx.x;
    red[tid] = v; __syncthreads();
    #pragma unroll
    for (int o = 128; o > 0; o >>= 1) { if (tid < o) red[tid] = fmaxf(red[tid], red[tid + o]); __syncthreads(); }
    float r = red[0]; __syncthreads();
    return r;
}

// ---------------- the megakernel ----------------
__global__ void __launch_bounds__(256, 1)
mega(const int* __restrict__ ing, const float* __restrict__ emb,
     const float* __restrict__ eWih, const float* __restrict__ eWhh,
     const float* __restrict__ ebih, const float* __restrict__ ebhh,
     const float* __restrict__ dWih, const float* __restrict__ dWhh,
     const float* __restrict__ dbih, const float* __restrict__ dbhh,
     const float* __restrict__ aW, const float* __restrict__ ab,
     const float* __restrict__ oW, const float* __restrict__ ob,
     float* __restrict__ out)
{
    extern __shared__ float dyn[];
    float* wsm = dyn;             // 3840 floats: enc (1536 used) / dec flattened rows
    float* buf = dyn + 3840;      // 20480 floats: [k][b] staging, k up to 640

    __shared__ float S[8][6][32];
    __shared__ float red[256];
    __shared__ float ws[128];
    __shared__ int   toks[BB];
    __shared__ unsigned long long slots[BB];

    const int c = blockIdx.x, tid = threadIdx.x;
    const int w = tid >> 5, lane = tid & 31;
    int nbar = 0;

    // ============ Phase X: zero h0, enc weights->smem, Xih precompute ============
    if (c == 0) for (int i = tid; i < BB*HH; i += 256) g_h[0][i] = 0.0f;
    if (c < 128) {
        // wenc[(jl*3+g)*256 + k] = eWhh[(g*256 + 2c+jl)*256 + k]
        for (int i = tid; i < 1536; i += 256) {
            int jlg = i >> 8, k = i & 255;
            int jl = jlg / 3, g = jlg % 3;
            wsm[i] = eWhh[(g*256 + 2*c + jl)*HH + k];
        }
    }
    for (int p = c; p < BB*SS; p += GRIDN) {
        __syncthreads();
        if (tid < EE) { int tok = ing[p]; buf[tid] = emb[tok*EE + tid]; }
        __syncthreads();
        const float4* x4 = (const float4*)buf;
        #pragma unroll
        for (int gi = 0; gi < 3; gi++) {
            int row = gi*256 + tid;
            const float4* w4 = (const float4*)(eWih + (size_t)row*EE);
            float a0 = ebih[row], a1 = 0.f, a2 = 0.f, a3 = 0.f;
            #pragma unroll
            for (int k = 0; k < EE/4; k++) {
                float4 ww = __ldg(&w4[k]); float4 xv = x4[k];
                a0 += ww.x*xv.x; a1 += ww.y*xv.y; a2 += ww.z*xv.z; a3 += ww.w*xv.w;
            }
            g_Xih[(size_t)p*G3 + row] = (a0+a1)+(a2+a3);
        }
    }
    gbar(nbar);

    // ============ Encoder: 100 steps ============
    for (int s = 0; s < SS; s++) {
        if (c < 128) {
            const float* hin = g_h[s & 1];
            for (int idx = tid; idx < BB*HH; idx += 256)
                buf[(idx & (HH-1))*32 + (idx >> 8)] = hin[idx];
            __syncthreads();
            float hreg[32];
            #pragma unroll
            for (int kk = 0; kk < 32; kk++) hreg[kk] = buf[(32*w + kk)*32 + lane];
            #pragma unroll
            for (int row = 0; row < 6; row++) {
                const float4* wv = (const float4*)(wsm + row*256 + 32*w);
                float a0=0,a1=0,a2=0,a3=0;
                #pragma unroll
                for (int i = 0; i < 8; i++) {
                    float4 x = wv[i];
                    a0 += x.x*hreg[4*i]; a1 += x.y*hreg[4*i+1];
                    a2 += x.z*hreg[4*i+2]; a3 += x.w*hreg[4*i+3];
                }
                S[w][row][lane] = (a0+a1)+(a2+a3);
            }
            __syncthreads();
            if (w < 2) {
                int j = 2*c + w, b = lane;
                float rs=0, zs=0, ns=0;
                #pragma unroll
                for (int ww = 0; ww < 8; ww++) {
                    rs += S[ww][w*3+0][b]; zs += S[ww][w*3+1][b]; ns += S[ww][w*3+2][b];
                }
                const float* gi = g_Xih + ((size_t)b*SS + s)*G3;
                float r = sigf(gi[j] + rs + ebhh[j]);
                float z = sigf(gi[HH + j] + zs + ebhh[HH + j]);
                float n = tanhf(gi[2*HH + j] + r*(ns + ebhh[2*HH + j]));
                float hprev = buf[j*32 + b];
                float h2 = (1.0f - z)*n + z*hprev;
                g_h[(s+1) & 1][b*HH + j] = h2;
                g_enc_outs[((size_t)b*SS + s)*HH + j] = h2;
            }
        }
        gbar(nbar);
    }

    // ============ enc_part + build decoder weight slice ============
    if (c < 128) {
        int j0 = 2*c;
        for (int g = tid; g < 3840; g += 256) {
            int jl = (g >= 1920) ? 1 : 0;
            int gg = g - jl*1920;
            int j = j0 + jl;
            int rl, k;
            if (gg < 640)       { rl = 0; k = gg; }
            else if (gg < 1280) { rl = 1; k = gg - 640; }
            else if (gg < 1664) { rl = 2; k = gg - 1280; }
            else                { rl = 3; k = gg - 1664; }
            float v;
            if (rl == 0)      v = (k < 384) ? dWih[(size_t)j*384 + k]          : dWhh[(size_t)j*HH + (k-384)];
            else if (rl == 1) v = (k < 384) ? dWih[(size_t)(256+j)*384 + k]    : dWhh[(size_t)(256+j)*HH + (k-384)];
            else if (rl == 2) v = dWih[(size_t)(512+j)*384 + k];
            else              v = dWhh[(size_t)(512+j)*HH + k];
            wsm[g] = v;
        }
    }
    {
        int gt = c*256 + tid;
        if (gt < BB*SS) {
            const float4* e4 = (const float4*)(g_enc_outs + (size_t)gt*HH);
            const float4* w4 = (const float4*)aW;
            float a0 = ab[0], a1=0,a2=0,a3=0;
            #pragma unroll 8
            for (int k = 0; k < HH/4; k++) {
                float4 e = e4[k]; float4 ww = __ldg(&w4[k]);
                a0 += e.x*ww.x; a1 += e.y*ww.y; a2 += e.z*ww.z; a3 += e.w*ww.w;
            }
            g_enc_part[gt] = (a0+a1)+(a2+a3);
        }
    }
    gbar(nbar);

    // ============ decoder loop ============
    static const int rowoff_[8] = {0,640,1280,1664,1920,2560,3200,3584};
    static const int s0row_[8] = {0,0,1,2,4,4,5,6};
    static const int s0k_[8]   = {0,480,320,160,0,480,320,160};
    static const int s0len_[8] = {480,160,320,224,480,160,320,224};
    static const int s1row_[8] = {0,1,2,3,4,5,6,7};
    static const int s1len_[8] = {0,320,160,256,0,320,160,256};

    // attention for a given h (also used pre-loop for t=0)
    auto do_attn = [&](const float* h) {
        int i = c - 125;
        int nb = (i + 23 < BB) ? 2 : 1;
        for (int q = 0; q < nb; q++) {
            int b = i + q*23;
            float p = h[b*HH + tid] * aW[HH + tid];
            float hw = rsum256(p, red);
            float sc = (tid < SS) ? (g_enc_part[b*SS + tid] + hw) : -1e30f;
            float mx = rmax256(sc, red);
            float e = (tid < SS) ? expf(sc - mx) : 0.0f;
            if (tid < 128) ws[tid] = (tid < SS) ? e : 0.0f;
            float inv = 1.0f / rsum256(e, red);
            __syncthreads();
            int j = tid;
            const float* eo = g_enc_outs + (size_t)b*SS*HH + j;
            float a0=0, a1=0;
            #pragma unroll 4
            for (int s = 0; s < SS; s += 2) {
                a0 += ws[s] * eo[(size_t)s*HH];
                a1 += ws[s+1] * eo[(size_t)(s+1)*HH];
            }
            g_ctx[b*HH + j] = (a0 + a1) * inv;
            __syncthreads();
        }
    };

    // attn for t=0 (needs h_enc = g_h[0])
    if (c >= 125) do_attn(g_h[0]);
    gbar(nbar);

    for (int t = 0; t < TT; t++) {
        // -------- P1: GRU --------
        if (c < 128) {
            if (tid < BB)
                toks[tid] = (t == 0) ? 1
                    : (int)(0xFFFFFFFFu - (unsigned)(g_amax[(t-1) & 1][tid] & 0xFFFFFFFFull));
            if (c == 0 && tid >= 32 && tid < 64) g_amax[t & 1][tid - 32] = 0ULL;
            __syncthreads();
            const float* hin = g_h[t & 1];
            // fill buf[640][32]
            #pragma unroll
            for (int i = 0; i < 20; i++) {
                int k4 = w*20 + i, k = 4*k4;
                float4 v;
                if (k4 < 32)       v = *(const float4*)(emb + (size_t)toks[lane]*EE + k);
                else if (k4 < 96)  v = *(const float4*)(g_ctx + lane*HH + (k - 128));
                else               v = *(const float4*)(hin + lane*HH + (k - 384));
                buf[(k+0)*32+lane]=v.x; buf[(k+1)*32+lane]=v.y;
                buf[(k+2)*32+lane]=v.z; buf[(k+3)*32+lane]=v.w;
            }
            __syncthreads();
            // segment partials
            {
                int r0 = s0row_[w], k0 = s0k_[w], l0 = s0len_[w];
                const float4* wv = (const float4*)(wsm + rowoff_[r0] + k0);
                int bo = (((r0 & 3) == 3) ? 384 : 0) + k0;
                float a0=0,a1=0,a2=0,a3=0;
                #pragma unroll 4
                for (int i = 0; i < l0/4; i++) {
                    float4 x = wv[i];
                    int kb = (bo + 4*i)*32 + lane;
                    a0 += x.x*buf[kb]; a1 += x.y*buf[kb+32];
                    a2 += x.z*buf[kb+64]; a3 += x.w*buf[kb+96];
                }
                S[w][0][lane] = (a0+a1)+(a2+a3);
            }
            {
                int r1 = s1row_[w], l1 = s1len_[w];
                float acc = 0.0f;
                if (l1 > 0) {
                    const float4* wv = (const float4*)(wsm + rowoff_[r1]);
                    int bo = ((r1 & 3) == 3) ? 384 : 0;
                    float a0=0,a1=0,a2=0,a3=0;
                    #pragma unroll 4
                    for (int i = 0; i < l1/4; i++) {
                        float4 x = wv[i];
                        int kb = (bo + 4*i)*32 + lane;
                        a0 += x.x*buf[kb]; a1 += x.y*buf[kb+32];
                        a2 += x.z*buf[kb+64]; a3 += x.w*buf[kb+96];
                    }
                    acc = (a0+a1)+(a2+a3);
                }
                S[w][1][lane] = acc;
            }
            __syncthreads();
            if (w == 0 || w == 4) {
                int jl = w >> 2, base = jl*4;
                int j = 2*c + jl, b = lane;
                float r_in = S[base+0][0][b] + S[base+1][0][b];
                float z_in = S[base+1][1][b] + S[base+2][0][b];
                float nx   = S[base+2][1][b] + S[base+3][0][b];
                float nh   = S[base+3][1][b];
                float r = sigf(r_in + dbih[j] + dbhh[j]);
                float z = sigf(z_in + dbih[HH + j] + dbhh[HH + j]);
                float n = tanhf(nx + dbih[2*HH + j] + r*(nh + dbhh[2*HH + j]));
                float hprev = buf[(384 + j)*32 + b];
                float h2 = (1.0f - z)*n + z*hprev;
                g_h[(t+1) & 1][b*HH + j] = h2;
            }
        }
        gbar(nbar);

        // -------- P2: logits+argmax (c<125) || attn t+1 (c>=125) --------
        if (c < 125) {
            const float* h = g_h[(t+1) & 1];
            if (tid < BB) slots[tid] = 0ULL;
            for (int idx = tid; idx < BB*HH; idx += 256)
                buf[(idx & (HH-1))*32 + (idx >> 8)] = h[idx];
            __syncthreads();

            int v = c*256 + tid;
            float bias = ob[v];
            unsigned long long acc[16];
            unsigned long long binit = pk2(bias, bias);
            #pragma unroll
            for (int i = 0; i < 16; i++) acc[i] = binit;

            const float4* w4 = (const float4*)(oW + (size_t)v*HH);
            #pragma unroll 2
            for (int k4 = 0; k4 < HH/4; k4++) {
                float4 wv = __ldg(&w4[k4]);
                const float wvv[4] = {wv.x, wv.y, wv.z, wv.w};
                #pragma unroll
                for (int sub = 0; sub < 4; sub++) {
                    unsigned long long ww = pk2(wvv[sub], wvv[sub]);
                    const ulonglong2* hp = (const ulonglong2*)(buf + (k4*4 + sub)*32);
                    #pragma unroll
                    for (int i = 0; i < 8; i++) {
                        ulonglong2 hv = hp[i];
                        acc[2*i]   = fma2(ww, hv.x, acc[2*i]);
                        acc[2*i+1] = fma2(ww, hv.y, acc[2*i+1]);
                    }
                }
            }
            float* outp = out + (size_t)t*VV;
            #pragma unroll
            for (int i = 0; i < 16; i++) {
                float f0, f1;
                upk2(acc[i], f0, f1);
                int b0 = 2*i, b1 = 2*i + 1;
                outp[(size_t)b0*TV + v] = f0;
                outp[(size_t)b1*TV + v] = f1;
                {
                    unsigned key = fkey(f0);
                    unsigned wmax = __reduce_max_sync(0xffffffffu, key);
                    unsigned mask = __ballot_sync(0xffffffffu, key == wmax);
                    if (lane == (__ffs(mask) - 1))
                        atomicMax(&slots[b0], ((unsigned long long)wmax << 32)
                                              | (unsigned long long)(0xFFFFFFFFu - (unsigned)v));
                }
                {
                    unsigned key = fkey(f1);
                    unsigned wmax = __reduce_max_sync(0xffffffffu, key);
                    unsigned mask = __ballot_sync(0xffffffffu, key == wmax);
                    if (lane == (__ffs(mask) - 1))
                        atomicMax(&slots[b1], ((unsigned long long)wmax << 32)
                                              | (unsigned long long)(0xFFFFFFFFu - (unsigned)v));
                }
            }
            __syncthreads();
            if (tid < BB) atomicMax(&g_amax[t & 1][tid], slots[tid]);
        } else if (t < TT-1) {
            do_attn(g_h[(t+1) & 1]);
        }
        gbar(nbar);
    }
}

// ---------------- host launch ----------------
extern "C" void kernel_launch(void* const* d_in, const int* in_sizes, int n_in,
                              void* d_out, int out_size) {
    const int*   ing      = (const int*)d_in[0];
    const float* emb      = (const float*)d_in[1];
    const float* enc_Wih  = (const float*)d_in[2];
    const float* enc_Whh  = (const float*)d_in[3];
    const float* enc_bih  = (const float*)d_in[4];
    const float* enc_bhh  = (const float*)d_in[5];
    const float* dec_Wih  = (const float*)d_in[6];
    const float* dec_Whh  = (const float*)d_in[7];
    const float* dec_bih  = (const float*)d_in[8];
    const float* dec_bhh  = (const float*)d_in[9];
    const float* attn_W   = (const float*)d_in[10];
    const float* attn_b   = (const float*)d_in[11];
    const float* out_W    = (const float*)d_in[12];
    const float* out_b    = (const float*)d_in[13];
    float* out = (float*)d_out;

    static int configured = 0;
    if (!configured) {
        cudaFuncSetAttribute(mega, cudaFuncAttributeMaxDynamicSharedMemorySize, 98304);
        configured = 1;
    }
    k_reset<<<1, 1>>>();
    mega<<<GRIDN, 256, 97280>>>(ing, emb, enc_Wih, enc_Whh, enc_bih, enc_bhh,
                                dec_Wih, dec_Whh, dec_bih, dec_bhh,
                                attn_W, attn_b, out_W, out_b, out);
}